// round 1
// baseline (speedup 1.0000x reference)
#include <cuda_runtime.h>

#define N_NODES 100000
#define N_EDGES 800000
#define F 64

// ---------------- scratch (device globals; no allocation allowed) ----------
__device__ float  g_h [N_NODES * F];
__device__ float  g_y [N_NODES * F];
__device__ float  g_hN[N_NODES * F];
__device__ int    g_deg[N_NODES];
__device__ int    g_off[N_NODES + 1];
__device__ int    g_cur[N_NODES];
__device__ float  g_invdeg[N_NODES];
__device__ int    g_csr_src[N_EDGES];
__device__ float4 g_csr_w [N_EDGES];

// ---------------- CSR build -------------------------------------------------
__global__ void hist_kernel(const int* __restrict__ dst) {
    int e = blockIdx.x * blockDim.x + threadIdx.x;
    if (e < N_EDGES) atomicAdd(&g_deg[dst[e]], 1);
}

__global__ void scan_kernel() {
    __shared__ int ssum[1024];
    int tid = threadIdx.x;
    const int CH = (N_NODES + 1023) / 1024;
    int st = tid * CH;
    int en = min(st + CH, N_NODES);
    int s = 0;
    for (int i = st; i < en; i++) s += g_deg[i];
    ssum[tid] = s;
    __syncthreads();
    // Hillis-Steele inclusive scan over 1024 partial sums
    for (int d = 1; d < 1024; d <<= 1) {
        int v = (tid >= d) ? ssum[tid - d] : 0;
        __syncthreads();
        ssum[tid] += v;
        __syncthreads();
    }
    int run = ssum[tid] - s;  // exclusive prefix of this thread's chunk
    for (int i = st; i < en; i++) {
        int dg = g_deg[i];
        g_off[i] = run;
        g_cur[i] = run;
        g_invdeg[i] = 1.0f / (float)max(dg, 1);
        run += dg;
    }
    if (tid == 1023) g_off[N_NODES] = run;
}

__global__ void fill_kernel(const int* __restrict__ src, const int* __restrict__ dst,
                            const float* __restrict__ si, const float* __restrict__ di,
                            const float* __restrict__ rv) {
    int e = blockIdx.x * blockDim.x + threadIdx.x;
    if (e >= N_EDGES) return;
    int d = dst[e];
    int pos = atomicAdd(&g_cur[d], 1);
    g_csr_src[pos] = src[e];
    g_csr_w[pos] = make_float4(si[e], di[e], rv[e], 0.0f);
}

// ---------------- embedding gather -----------------------------------------
__global__ void embed_kernel(const int* __restrict__ gt, const float* __restrict__ emb,
                             float* __restrict__ h) {
    int idx = blockIdx.x * blockDim.x + threadIdx.x;
    if (idx >= N_NODES * (F / 4)) return;
    int n = idx >> 4;          // F/4 = 16 float4 per row
    int c = idx & 15;
    ((float4*)h)[(size_t)n * 16 + c] =
        ((const float4*)emb)[(size_t)gt[n] * 16 + c];
}

// ---------------- skinny node GEMM: out = act(A1|A2 @ W^T + b) --------------
// W is [CO x (K1+K2)] with row stride ldw. One thread = one node row.
template <int K1, int K2, int CO, bool RELU>
__global__ void gemm_kernel(const float* __restrict__ A1, const float* __restrict__ A2,
                            const float* __restrict__ W, int ldw,
                            const float* __restrict__ bias,
                            float* __restrict__ out) {
    constexpr int K = K1 + K2;
    __shared__ float sWt[K * CO];  // transposed: sWt[k*CO + o]
    for (int idx = threadIdx.x; idx < K * CO; idx += blockDim.x) {
        int k = idx / CO, o = idx - k * CO;
        sWt[idx] = W[o * ldw + k];
    }
    __syncthreads();

    int node = blockIdx.x * blockDim.x + threadIdx.x;
    if (node >= N_NODES) return;

    float acc[CO];
#pragma unroll
    for (int o = 0; o < CO; o++) acc[o] = bias ? __ldg(&bias[o]) : 0.0f;

    const float4* a1 = (const float4*)(A1 + (size_t)node * K1);
#pragma unroll 1
    for (int kk = 0; kk < K1 / 4; kk++) {
        float4 a = a1[kk];
        const float* w0 = &sWt[(4 * kk + 0) * CO];
        const float* w1 = &sWt[(4 * kk + 1) * CO];
        const float* w2 = &sWt[(4 * kk + 2) * CO];
        const float* w3 = &sWt[(4 * kk + 3) * CO];
#pragma unroll
        for (int o = 0; o < CO; o++) {
            float v = acc[o];
            v = fmaf(a.x, w0[o], v);
            v = fmaf(a.y, w1[o], v);
            v = fmaf(a.z, w2[o], v);
            v = fmaf(a.w, w3[o], v);
            acc[o] = v;
        }
    }
    if (K2 > 0) {
        const float4* a2 = (const float4*)(A2 + (size_t)node * K2);
#pragma unroll 1
        for (int kk = 0; kk < K2 / 4; kk++) {
            float4 a = a2[kk];
            const float* w0 = &sWt[(K1 + 4 * kk + 0) * CO];
            const float* w1 = &sWt[(K1 + 4 * kk + 1) * CO];
            const float* w2 = &sWt[(K1 + 4 * kk + 2) * CO];
            const float* w3 = &sWt[(K1 + 4 * kk + 3) * CO];
#pragma unroll
            for (int o = 0; o < CO; o++) {
                float v = acc[o];
                v = fmaf(a.x, w0[o], v);
                v = fmaf(a.y, w1[o], v);
                v = fmaf(a.z, w2[o], v);
                v = fmaf(a.w, w3[o], v);
                acc[o] = v;
            }
        }
    }

    float4* op = (float4*)(out + (size_t)node * CO);
#pragma unroll
    for (int oc = 0; oc < CO / 4; oc++) {
        float4 v;
        v.x = acc[4 * oc + 0]; v.y = acc[4 * oc + 1];
        v.z = acc[4 * oc + 2]; v.w = acc[4 * oc + 3];
        if (RELU) {
            v.x = fmaxf(v.x, 0.0f); v.y = fmaxf(v.y, 0.0f);
            v.z = fmaxf(v.z, 0.0f); v.w = fmaxf(v.w, 0.0f);
        }
        op[oc] = v;
    }
}

// ---------------- edge aggregation (gather-side, no atomics) ----------------
// One warp per dst node; each lane owns 2 output features.
// tmp_e = leaky_relu(y[src_e] + W1[:,64]*si + W1[:,65]*di + W1[:,66]*rv)
// h_N[d] = inv_deg[d] * sum_{e: dst=d} tmp_e
__global__ void edge_kernel(const float* __restrict__ W1i) {
    int gid = blockIdx.x * blockDim.x + threadIdx.x;
    int node = gid >> 5;
    int lane = gid & 31;
    if (node >= N_NODES) return;

    int o0 = 2 * lane, o1 = 2 * lane + 1;
    float ax = __ldg(&W1i[o0 * 67 + 64]), ay = __ldg(&W1i[o1 * 67 + 64]);
    float bx = __ldg(&W1i[o0 * 67 + 65]), by = __ldg(&W1i[o1 * 67 + 65]);
    float cx = __ldg(&W1i[o0 * 67 + 66]), cy = __ldg(&W1i[o1 * 67 + 66]);

    float accx = 0.0f, accy = 0.0f;
    int jb = g_off[node], je = g_off[node + 1];
    for (int j = jb; j < je; j++) {
        int s = g_csr_src[j];           // broadcast load (same addr per warp)
        float4 wv = g_csr_w[j];         // broadcast load
        float2 yv = *(const float2*)&g_y[(size_t)s * F + 2 * lane];
        float tx = fmaf(ax, wv.x, fmaf(bx, wv.y, fmaf(cx, wv.z, yv.x)));
        float ty = fmaf(ay, wv.x, fmaf(by, wv.y, fmaf(cy, wv.z, yv.y)));
        tx = (tx >= 0.0f) ? tx : 0.01f * tx;
        ty = (ty >= 0.0f) ? ty : 0.01f * ty;
        accx += tx;
        accy += ty;
    }
    float id = g_invdeg[node];
    float2 r;
    r.x = accx * id;
    r.y = accy * id;
    *(float2*)&g_hN[(size_t)node * F + 2 * lane] = r;
}

// ---------------- launch -----------------------------------------------------
extern "C" void kernel_launch(void* const* d_in, const int* in_sizes, int n_in,
                              void* d_out, int out_size) {
    const int*   gate_type = (const int*)  d_in[0];
    const int*   src       = (const int*)  d_in[1];
    const int*   dst       = (const int*)  d_in[2];
    const float* src_idx   = (const float*)d_in[3];
    const float* dst_idx   = (const float*)d_in[4];
    const float* rev       = (const float*)d_in[5];
    const float* emb       = (const float*)d_in[6];
    const float* W1        = (const float*)d_in[7];   // [5,64,67]
    const float* W2        = (const float*)d_in[8];   // [5,64,128]
    const float* b2        = (const float*)d_in[9];   // [5,64]
    const float* Wl1       = (const float*)d_in[10];  // [64,64]
    const float* bl1       = (const float*)d_in[11];  // [64]
    const float* Wl2       = (const float*)d_in[12];  // [32,64]
    const float* bl2       = (const float*)d_in[13];  // [32]
    float*       out       = (float*)d_out;

    float *ph, *py, *phN;
    int* pdeg;
    cudaGetSymbolAddress((void**)&ph,   g_h);
    cudaGetSymbolAddress((void**)&py,   g_y);
    cudaGetSymbolAddress((void**)&phN,  g_hN);
    cudaGetSymbolAddress((void**)&pdeg, g_deg);

    // CSR build (once per launch; identical inputs -> identical result)
    cudaMemsetAsync(pdeg, 0, N_NODES * sizeof(int));
    hist_kernel<<<(N_EDGES + 255) / 256, 256>>>(dst);
    scan_kernel<<<1, 1024>>>();
    fill_kernel<<<(N_EDGES + 255) / 256, 256>>>(src, dst, src_idx, dst_idx, rev);

    // h0 = emb[gate_type]
    embed_kernel<<<(N_NODES * (F / 4) + 255) / 256, 256>>>(gate_type, emb, ph);

    const int GEMM_BLOCKS = (N_NODES + 255) / 256;
    const int EDGE_BLOCKS = (N_NODES * 32 + 255) / 256;

    for (int i = 0; i < 5; i++) {
        const float* W1i = W1 + (size_t)i * 64 * 67;
        const float* W2i = W2 + (size_t)i * 64 * 128;
        const float* b2i = b2 + (size_t)i * 64;

        // y = h @ W1[:, :64]^T   (node-only part of the edge MLP)
        gemm_kernel<64, 0, 64, false><<<GEMM_BLOCKS, 256>>>(ph, nullptr, W1i, 67, nullptr, py);
        // h_N = mean_{in-edges} leaky_relu(y[src] + W1w @ w)
        edge_kernel<<<EDGE_BLOCKS, 256>>>(W1i);
        // h = relu([h, h_N] @ W2^T + b2)   (in-place: each thread owns a full row)
        gemm_kernel<64, 64, 64, true><<<GEMM_BLOCKS, 256>>>(ph, phN, W2i, 128, b2i, ph);
    }

    // heads
    gemm_kernel<64, 0, 64, true ><<<GEMM_BLOCKS, 256>>>(ph, nullptr, Wl1, 64, bl1, py);
    gemm_kernel<64, 0, 32, false><<<GEMM_BLOCKS, 256>>>(py, nullptr, Wl2, 64, bl2, out);
}